// round 13
// baseline (speedup 1.0000x reference)
#include <cuda_runtime.h>
#include <cstdint>

typedef unsigned long long u64;

#define NB      16
#define EMB     208
#define KLV     300
#define NPROP   900
#define MAXP    500
#define DPROP   213
#define NWORDS  15      // ceil(900/64)
#define NMS_THR 0.45f
#define NBIN    2048
#define DSZ     30324   // 23104 + 5776 + 1444 per image

__constant__ float2 c_anch[3][4] = {
  {{8.f,24.f},{11.f,34.f},{16.f,48.f},{23.f,68.f}},
  {{32.f,96.f},{45.f,135.f},{64.f,192.f},{90.f,271.f}},
  {{128.f,384.f},{180.f,540.f},{256.f,640.f},{512.f,640.f}}
};
__constant__ int   c_H[3]    = {76, 38, 19};
__constant__ int   c_N[3]    = {23104, 5776, 1444};
__constant__ int   c_off[3]  = {0, 23104, 28880};
__constant__ float c_stride[3] = {8.f, 16.f, 32.f};

// ---------------- device scratch (no allocations allowed) ----------------
__device__ float    g_ds[NB*DSZ];              // d = logit_c - logit_a, [b][r]
__device__ unsigned g_hist[3*NB*NBIN];         // zero-init; re-zeroed each launch
__device__ float4 g_box[NB*NPROP];
__device__ float  g_score[NB*NPROP];
__device__ int    g_src[NB*NPROP];
__device__ float4 g_sbox[NB*NPROP];
__device__ float  g_sscore[NB*NPROP];
__device__ int    g_ssrc[NB*NPROP];
__device__ int    g_nvalid[NB];
__device__ u64    g_supp[NB*NPROP*NWORDS];
__device__ int    g_kept[NB*MAXP];
__device__ int    g_nkept[NB];

// ---- 1a) chip-wide: d = c - a into g_ds + global per-(b,level) histogram ----
__global__ void hist_kernel(const float* __restrict__ p0,
                            const float* __restrict__ p1,
                            const float* __restrict__ p2)
{
  int gid = blockIdx.x*blockDim.x + threadIdx.x;
  if (gid >= NB*DSZ) return;
  int b = gid / DSZ;
  int r = gid - b*DSZ;
  int level, i;
  const float* pred;
  if (r < 23104)      { level = 0; i = r;         pred = p0; }
  else if (r < 28880) { level = 1; i = r - 23104; pred = p1; }
  else                { level = 2; i = r - 28880; pred = p2; }
  const float* pb = pred + (size_t)b * c_N[level] * 6;
  float2 v = *(const float2*)(pb + (size_t)i*6 + 4);
  float d = v.y - v.x;
  g_ds[gid] = d;
  if (d > 0.0f) {
    int bin = (int)(d * 128.0f);
    bin = bin > NBIN-1 ? NBIN-1 : bin;
    atomicAdd(&g_hist[(level*NB + b)*NBIN + bin], 1u);
  }
}

// ---- 1b) per-(image,level): threshold from hist, collect, sort, decode ----
__global__ void select_kernel(const float* __restrict__ p0,
                              const float* __restrict__ p1,
                              const float* __restrict__ p2)
{
  const int b     = blockIdx.x;
  const int level = blockIdx.y;
  const int tid   = threadIdx.x;
  const int BS    = blockDim.x;           // 1024

  const float* pred = (level == 0) ? p0 : (level == 1) ? p1 : p2;
  const int H = c_H[level], W = H;
  const int N = c_N[level];
  const float stride = c_stride[level];
  const float scale  = stride / 608.0f;

  __shared__ unsigned int hist[NBIN];
  __shared__ unsigned int csum[64];
  __shared__ float cs[NBIN];
  __shared__ int   ci[NBIN];
  __shared__ int   s_cnt, s_tbin;

  // load histogram; re-zero global for next replay (determinism invariant)
  unsigned* gh = &g_hist[(level*NB + b)*NBIN];
  for (int i = tid; i < NBIN; i += BS) { hist[i] = gh[i]; gh[i] = 0u; }
  if (tid == 0) s_cnt = 0;
  __syncthreads();

  if (tid < 64) {
    unsigned s = 0;
    #pragma unroll
    for (int k = 0; k < 32; k++) s += hist[tid*32 + k];
    csum[tid] = s;
  }
  __syncthreads();
  if (tid == 0) {
    unsigned acc = 0;
    int t = 0;
    int c = 63;
    for (; c >= 0; c--) {
      if (acc + csum[c] >= (unsigned)KLV) break;
      acc += csum[c];
    }
    if (c >= 0) {
      int bb = c*32 + 31;
      for (; bb > c*32; bb--) {
        if (acc + hist[bb] >= (unsigned)KLV) break;
        acc += hist[bb];
      }
      t = bb;
    }
    s_tbin = t;
  }
  __syncthreads();
  const int t = s_tbin;

  // pass 2: coalesced scan of g_ds slice, collect candidates in bins >= t
  const float* dsrc = &g_ds[(size_t)b*DSZ + c_off[level]];
  for (int i = tid; i < N; i += BS) {
    float d = dsrc[i];
    if (d > 0.0f) {
      int bin = (int)(d * 128.0f);
      bin = bin > NBIN-1 ? NBIN-1 : bin;
      if (bin >= t) {
        int p = atomicAdd(&s_cnt, 1);
        if (p < NBIN) { cs[p] = d; ci[p] = i; }
      }
    }
  }
  __syncthreads();
  int m = s_cnt; if (m > NBIN) m = NBIN;

  // exact conf (matches reference softmax bitwise) for candidates only
  for (int p = tid; p < m; p += BS) {
    float conf = 1.0f / (1.0f + expf(-cs[p]));
    cs[p] = (conf > 0.5f) ? conf : -1.0f;
  }
  int P = 512; while (P < m) P <<= 1;
  for (int i = tid; i < P; i += BS)
    if (i >= m) { cs[i] = -1.0f; ci[i] = 0x7fffffff; }
  __syncthreads();

  // bitonic sort (conf desc, idx asc) over P elements
  for (int k = 2; k <= P; k <<= 1) {
    for (int j = k >> 1; j > 0; j >>= 1) {
      for (int x = tid; x < P; x += BS) {
        int ixj = x ^ j;
        if (ixj > x) {
          float ca = cs[x], cb = cs[ixj];
          int   ia = ci[x], ib = ci[ixj];
          bool later = (ca < cb) || (ca == cb && ia > ib);
          if (later == ((x & k) == 0)) {
            cs[x] = cb; cs[ixj] = ca;
            ci[x] = ib; ci[ixj] = ia;
          }
        }
      }
      __syncthreads();
    }
  }

  // decode + write top-300 (zero-pad shortfall / sub-threshold)
  const float* pb = pred + (size_t)b * N * 6;
  if (tid < KLV) {
    const int o = b*NPROP + level*KLV + tid;
    if (tid < m && cs[tid] > 0.5f) {
      float conf = cs[tid];
      int   idx  = ci[tid];
      int hw = H*W;
      int a  = idx / hw;
      int r2 = idx - a*hw;
      int h  = r2 / W;
      int w  = r2 - h*W;
      const float* pp = pb + (size_t)idx*6;
      float aw = c_anch[level][a].x / stride;
      float ah = c_anch[level][a].y / stride;
      float x  = pp[0]*aw + (float)w;
      float y  = pp[1]*ah + (float)h;
      float bw = expf(pp[2])*aw;
      float bh = expf(pp[3])*ah;
      float x1 = fminf(fmaxf((x - 0.5f*bw)*scale, 0.0f), 1.0f);
      float y1 = fminf(fmaxf((y - 0.5f*bh)*scale, 0.0f), 1.0f);
      float x2 = fminf(fmaxf((x + 0.5f*bw)*scale, 0.0f), 1.0f);
      float y2 = fminf(fmaxf((y + 0.5f*bh)*scale, 0.0f), 1.0f);
      g_box[o]   = make_float4(x1, y1, x2, y2);
      g_score[o] = conf;
      g_src[o]   = (level << 26) | idx;
    } else {
      g_box[o]   = make_float4(0.f, 0.f, 0.f, 0.f);
      g_score[o] = 0.f;
      g_src[o]   = -1;
    }
  }
}

// ---------------- 2) stable 3-way merge of sorted level lists ----------------
__global__ void merge_kernel()
{
  const int b = blockIdx.x;
  const int t = threadIdx.x;   // 1024
  __shared__ float s[NPROP];
  __shared__ float ms[2*KLV];
  __shared__ int   p6[2*KLV];
  __shared__ float fs[NPROP];
  __shared__ int   p9[NPROP];
  __shared__ int   s_nv;

  if (t < NPROP) s[t] = g_score[b*NPROP + t];
  if (t == 0) s_nv = 0;
  __syncthreads();

  // stage 1: merge [0,300) (A) with [300,600) (B); A wins ties
  if (t < 2*KLV) {
    float v; int pos;
    if (t < KLV) {
      v = s[t];
      int lo = 0, hi = KLV;
      while (lo < hi) { int mid = (lo+hi)>>1; if (s[KLV+mid] > v) lo = mid+1; else hi = mid; }
      pos = t + lo;
    } else {
      int j = t - KLV; v = s[t];
      int lo = 0, hi = KLV;
      while (lo < hi) { int mid = (lo+hi)>>1; if (s[mid] >= v) lo = mid+1; else hi = mid; }
      pos = j + lo;
    }
    ms[pos] = v; p6[pos] = t;
  }
  __syncthreads();

  // stage 2: merge AB (600) with C = [600,900); AB wins ties
  if (t < NPROP) {
    float v; int src, pos;
    if (t < 2*KLV) {
      v = ms[t]; src = p6[t];
      int lo = 0, hi = KLV;
      while (lo < hi) { int mid = (lo+hi)>>1; if (s[2*KLV+mid] > v) lo = mid+1; else hi = mid; }
      pos = t + lo;
    } else {
      int j = t - 2*KLV; v = s[t]; src = t;
      int lo = 0, hi = 2*KLV;
      while (lo < hi) { int mid = (lo+hi)>>1; if (ms[mid] >= v) lo = mid+1; else hi = mid; }
      pos = j + lo;
    }
    fs[pos] = v; p9[pos] = src;
  }
  __syncthreads();

  if (t < NPROP) {
    int src = p9[t];
    g_sbox[b*NPROP + t]   = g_box[b*NPROP + src];
    g_sscore[b*NPROP + t] = fs[t];
    g_ssrc[b*NPROP + t]   = g_src[b*NPROP + src];
    if (fs[t] > 0.f && (t == NPROP-1 || fs[t+1] <= 0.f)) s_nv = t + 1;
  }
  __syncthreads();
  if (t == 0) g_nvalid[b] = s_nv;
}

// ------- 3) suppression bitmatrix: one wave, strided rows, guard classes -------
__global__ void supp_kernel()
{
  const int b     = blockIdx.y;
  const int slice = blockIdx.x;        // 0..8
  const int t     = threadIdx.x;       // 1024 = 32 warps
  __shared__ float sx1[NPROP], sy1[NPROP], sx2[NPROP], sy2[NPROP], sa[NPROP];
  for (int i = t; i < NPROP; i += 1024) {
    float4 f = g_sbox[b*NPROP + i];
    sx1[i] = f.x; sy1[i] = f.y; sx2[i] = f.z; sy2[i] = f.w;
    sa[i]  = (f.z - f.x) * (f.w - f.y);
  }
  __syncthreads();

  const int warp = t >> 5;
  const int lane = t & 31;

  // 100 rows x 15 words = 1500 tasks per block
  for (int task = warp; task < 100*NWORDS; task += 32) {
    int k = task / NWORDS;
    int w = task - k*NWORDS;
    int i = slice + 9*k;               // < 900 always (slice<9, k<100)
    u64* dst = &g_supp[((size_t)b*NPROP + i)*NWORDS + w];
    int j0 = w << 6;
    if (j0 + 63 <= i) {                // whole word in lower triangle
      if (lane == 0) *dst = 0ULL;
      continue;
    }
    float bx1 = sx1[i], by1 = sy1[i], bx2 = sx2[i], by2 = sy2[i], ai = sa[i];
    int j1 = j0 + lane;
    int j2 = j1 + 32;
    bool s1, s2;
    if (j0 > i && w != NWORDS-1) {     // interior word: guard-free (warp-uniform)
      {
        float xx1 = fmaxf(bx1, sx1[j1]);
        float yy1 = fmaxf(by1, sy1[j1]);
        float xx2 = fminf(bx2, sx2[j1]);
        float yy2 = fminf(by2, sy2[j1]);
        float inter = fmaxf(xx2 - xx1, 0.f) * fmaxf(yy2 - yy1, 0.f);
        s1 = inter > NMS_THR * (ai + sa[j1] - inter + 1e-9f);
      }
      {
        float xx1 = fmaxf(bx1, sx1[j2]);
        float yy1 = fmaxf(by1, sy1[j2]);
        float xx2 = fminf(bx2, sx2[j2]);
        float yy2 = fminf(by2, sy2[j2]);
        float inter = fmaxf(xx2 - xx1, 0.f) * fmaxf(yy2 - yy1, 0.f);
        s2 = inter > NMS_THR * (ai + sa[j2] - inter + 1e-9f);
      }
    } else {                           // diagonal or tail word
      s1 = false; s2 = false;
      if (j1 > i && j1 < NPROP) {
        float xx1 = fmaxf(bx1, sx1[j1]);
        float yy1 = fmaxf(by1, sy1[j1]);
        float xx2 = fminf(bx2, sx2[j1]);
        float yy2 = fminf(by2, sy2[j1]);
        float inter = fmaxf(xx2 - xx1, 0.f) * fmaxf(yy2 - yy1, 0.f);
        s1 = inter > NMS_THR * (ai + sa[j1] - inter + 1e-9f);
      }
      if (j2 > i && j2 < NPROP) {
        float xx1 = fmaxf(bx1, sx1[j2]);
        float yy1 = fmaxf(by1, sy1[j2]);
        float xx2 = fminf(bx2, sx2[j2]);
        float yy2 = fminf(by2, sy2[j2]);
        float inter = fmaxf(xx2 - xx1, 0.f) * fmaxf(yy2 - yy1, 0.f);
        s2 = inter > NMS_THR * (ai + sa[j2] - inter + 1e-9f);
      }
    }
    unsigned m1 = __ballot_sync(0xffffffffu, s1);
    unsigned m2 = __ballot_sync(0xffffffffu, s2);
    if (lane == 0) *dst = (u64)m1 | ((u64)m2 << 32);
  }
}

// ------- 4) greedy walk: warp 0, word-ordered + suppressor-word PREFETCH -------
// Invariant (word-ordered): rem[w] is final when word w starts. Within a word,
// the next candidate bit nb = ffs(cur & (cur-1)) depends only on cur — NOT on
// the current pick's suppressor word sw. So S(nb) is prefetched before ~sw is
// applied; when sw doesn't suppress nb (common case), the next iteration's
// suppressor word is already in flight and the 29-cyc LDS hides under ALU.
__global__ void greedy_kernel()
{
  const int b = blockIdx.x;
  extern __shared__ u64 ssup[];   // 900*15 u64 = 108000 B
  for (int x = threadIdx.x; x < NPROP*NWORDS; x += blockDim.x)
    ssup[x] = g_supp[(size_t)b*NPROP*NWORDS + x];
  __syncthreads();
  if (threadIdx.x >= 32) return;

  const int lane  = threadIdx.x;
  const int lanec = lane < NWORDS ? lane : NWORDS-1;   // clamped accumulate idx
  const int nv    = g_nvalid[b];
  const int nvw   = nv >> 6, nvb = nv & 63;
  u64 valid = (lane < nvw) ? ~0ULL
            : (lane == nvw ? (nvb ? ((1ULL << nvb) - 1ULL) : 0ULL) : 0ULL);
  u64 rem = ~valid;
  int nk = 0;

  for (int w = 0; w < NWORDS && nk < MAXP; w++) {
    const u64* base = ssup + ((size_t)w << 6) * NWORDS;   // row (w*64) start
    u64 cur = ~__shfl_sync(0xffffffffu, rem, w);          // final avail mask
    if (cur == 0) continue;
    int bit = __ffsll((long long)cur) - 1;
    u64 sw  = base[bit*NWORDS + w];                       // suppressor word of pick
    while (true) {
      // commit pick `bit` (lowest set bit of cur, sw = its word-w row entry)
      if (lane == 0) g_kept[b*MAXP + nk] = (w << 6) + bit;
      nk++;
      rem |= base[bit*NWORDS + lanec];                    // off critical path
      if (nk >= MAXP) break;

      u64 nraw = cur & (cur - 1);                         // drop picked bit
      if (nraw == 0) break;
      int nb  = __ffsll((long long)nraw) - 1;             // candidate (pre-sw)
      u64 nsw = base[nb*NWORDS + w];                      // PREFETCH (no sw dep)
      u64 ncur = nraw & ~sw;                              // apply suppression
      if (ncur == 0) break;
      int nb2 = __ffsll((long long)ncur) - 1;
      if (nb2 != nb) nsw = base[nb2*NWORDS + w];          // mispredict reload
      cur = ncur; bit = nb2; sw = nsw;
    }
  }
  if (lane == 0) g_nkept[b] = nk;
}

// ------- 5) output: warp-per-row gather + L2-normalize + write (chip-wide) -------
__global__ void write_kernel(float* __restrict__ out,
                             const float* __restrict__ e0,
                             const float* __restrict__ e1,
                             const float* __restrict__ e2)
{
  const int b    = blockIdx.y;
  const int warp = threadIdx.x >> 5;      // 16 warps
  const int lane = threadIdx.x & 31;
  const int r    = blockIdx.x * 16 + warp;  // 32 x 16 = 512 >= 500 rows
  if (r >= MAXP) return;

  float* o = out + ((size_t)b*MAXP + r)*DPROP;

  if (r >= g_nkept[b]) {                  // zero row (output is poisoned)
    #pragma unroll
    for (int k = 0; k < 7; k++) {
      int e = lane + k*32;
      if (e < DPROP) o[e] = 0.0f;
    }
    return;
  }

  const int i   = g_kept[b*MAXP + r];
  const int src = g_ssrc[b*NPROP + i];
  const int level = src >> 26;
  const int idx   = src & ((1 << 26) - 1);
  const int H  = (level == 0) ? 76 : (level == 1 ? 38 : 19);
  const int hw = H*H;
  const int r2 = idx % hw;
  const int h  = r2 / H;
  const int w  = r2 - h*H;
  const float* eb = (level == 0 ? e0 : (level == 1 ? e1 : e2));
  const float* e  = eb + (((size_t)b*H + h)*H + w)*EMB;

  float v[7];
  float p = 0.0f;
  #pragma unroll
  for (int k = 0; k < 7; k++) {
    int x = lane + k*32;
    v[k] = (x < EMB) ? e[x] : 0.0f;
    p += v[k]*v[k];
  }
  #pragma unroll
  for (int s = 16; s > 0; s >>= 1) p += __shfl_xor_sync(0xffffffffu, p, s);
  float rinv = rsqrtf(fmaxf(p, 1e-12f));

  #pragma unroll
  for (int k = 0; k < 7; k++) {
    int x = lane + k*32;
    if (x < EMB) o[5 + x] = v[k] * rinv;
  }
  if (lane == 0) {
    float4 bx = g_sbox[b*NPROP + i];
    o[0] = bx.x; o[1] = bx.y; o[2] = bx.z; o[3] = bx.w;
    o[4] = g_sscore[b*NPROP + i];
  }
}

// ---------------------------------------------------------------------------
extern "C" void kernel_launch(void* const* d_in, const int* in_sizes, int n_in,
                              void* d_out, int out_size)
{
  const float *p0=nullptr,*p1=nullptr,*p2=nullptr,*e0=nullptr,*e1=nullptr,*e2=nullptr;
  for (int i = 0; i < n_in; i++) {
    switch (in_sizes[i]) {
      case 2217984:  p0 = (const float*)d_in[i]; break;  // pred0 [16,4,76,76,6]
      case 554496:   p1 = (const float*)d_in[i]; break;  // pred1 [16,4,38,38,6]
      case 138624:   p2 = (const float*)d_in[i]; break;  // pred2 [16,4,19,19,6]
      case 19222528: e0 = (const float*)d_in[i]; break;  // emb0 [16,76,76,208]
      case 4805632:  e1 = (const float*)d_in[i]; break;  // emb1 [16,38,38,208]
      case 1201408:  e2 = (const float*)d_in[i]; break;  // emb2 [16,19,19,208]
    }
  }

  hist_kernel<<<(NB*DSZ + 1023)/1024, 1024>>>(p0, p1, p2);
  select_kernel<<<dim3(NB,3), 1024>>>(p0, p1, p2);
  merge_kernel<<<NB, 1024>>>();
  supp_kernel<<<dim3(9, NB), 1024>>>();

  cudaFuncSetAttribute(greedy_kernel, cudaFuncAttributeMaxDynamicSharedMemorySize,
                       NPROP*NWORDS*(int)sizeof(u64));
  greedy_kernel<<<NB, 1024, NPROP*NWORDS*sizeof(u64)>>>();

  write_kernel<<<dim3(32, NB), 512>>>((float*)d_out, e0, e1, e2);
}

// round 14
// speedup vs baseline: 1.3237x; 1.3237x over previous
#include <cuda_runtime.h>
#include <cstdint>

typedef unsigned long long u64;

#define NB      16
#define EMB     208
#define KLV     300
#define NPROP   900
#define MAXP    500
#define DPROP   213
#define NWORDS  15      // ceil(900/64)
#define NMS_THR 0.45f
#define NBIN    2048
#define DSZ     30324   // 23104 + 5776 + 1444 per image

__constant__ float2 c_anch[3][4] = {
  {{8.f,24.f},{11.f,34.f},{16.f,48.f},{23.f,68.f}},
  {{32.f,96.f},{45.f,135.f},{64.f,192.f},{90.f,271.f}},
  {{128.f,384.f},{180.f,540.f},{256.f,640.f},{512.f,640.f}}
};
__constant__ int   c_H[3]    = {76, 38, 19};
__constant__ int   c_N[3]    = {23104, 5776, 1444};
__constant__ int   c_off[3]  = {0, 23104, 28880};
__constant__ float c_stride[3] = {8.f, 16.f, 32.f};

// ---------------- device scratch (no allocations allowed) ----------------
__device__ float    g_ds[NB*DSZ];              // d = logit_c - logit_a, [b][r]
__device__ unsigned g_hist[3*NB*NBIN];         // zero-init; re-zeroed each launch
__device__ float4 g_box[NB*NPROP];
__device__ float  g_score[NB*NPROP];
__device__ int    g_src[NB*NPROP];
__device__ float4 g_sbox[NB*NPROP];
__device__ float  g_sscore[NB*NPROP];
__device__ int    g_ssrc[NB*NPROP];
__device__ int    g_nvalid[NB];
__device__ u64    g_supp[NB*NPROP*NWORDS];
__device__ int    g_kept[NB*MAXP];
__device__ int    g_nkept[NB];

// ---- 1a) chip-wide: d = c - a into g_ds + global per-(b,level) histogram ----
__global__ void hist_kernel(const float* __restrict__ p0,
                            const float* __restrict__ p1,
                            const float* __restrict__ p2)
{
  int gid = blockIdx.x*blockDim.x + threadIdx.x;
  if (gid >= NB*DSZ) return;
  int b = gid / DSZ;
  int r = gid - b*DSZ;
  int level, i;
  const float* pred;
  if (r < 23104)      { level = 0; i = r;         pred = p0; }
  else if (r < 28880) { level = 1; i = r - 23104; pred = p1; }
  else                { level = 2; i = r - 28880; pred = p2; }
  const float* pb = pred + (size_t)b * c_N[level] * 6;
  float2 v = *(const float2*)(pb + (size_t)i*6 + 4);
  float d = v.y - v.x;
  g_ds[gid] = d;
  if (d > 0.0f) {
    int bin = (int)(d * 128.0f);
    bin = bin > NBIN-1 ? NBIN-1 : bin;
    atomicAdd(&g_hist[(level*NB + b)*NBIN + bin], 1u);
  }
}

// ---- 1b) per-(image,level): threshold from hist, collect, sort, decode ----
__global__ void select_kernel(const float* __restrict__ p0,
                              const float* __restrict__ p1,
                              const float* __restrict__ p2)
{
  const int b     = blockIdx.x;
  const int level = blockIdx.y;
  const int tid   = threadIdx.x;
  const int BS    = blockDim.x;           // 1024

  const float* pred = (level == 0) ? p0 : (level == 1) ? p1 : p2;
  const int H = c_H[level], W = H;
  const int N = c_N[level];
  const float stride = c_stride[level];
  const float scale  = stride / 608.0f;

  __shared__ unsigned int hist[NBIN];
  __shared__ unsigned int csum[64];
  __shared__ float cs[NBIN];
  __shared__ int   ci[NBIN];
  __shared__ int   s_cnt, s_tbin;

  // load histogram; re-zero global for next replay (determinism invariant)
  unsigned* gh = &g_hist[(level*NB + b)*NBIN];
  for (int i = tid; i < NBIN; i += BS) { hist[i] = gh[i]; gh[i] = 0u; }
  if (tid == 0) s_cnt = 0;
  __syncthreads();

  if (tid < 64) {
    unsigned s = 0;
    #pragma unroll
    for (int k = 0; k < 32; k++) s += hist[tid*32 + k];
    csum[tid] = s;
  }
  __syncthreads();
  if (tid == 0) {
    unsigned acc = 0;
    int t = 0;
    int c = 63;
    for (; c >= 0; c--) {
      if (acc + csum[c] >= (unsigned)KLV) break;
      acc += csum[c];
    }
    if (c >= 0) {
      int bb = c*32 + 31;
      for (; bb > c*32; bb--) {
        if (acc + hist[bb] >= (unsigned)KLV) break;
        acc += hist[bb];
      }
      t = bb;
    }
    s_tbin = t;
  }
  __syncthreads();
  const int t = s_tbin;

  // pass 2: coalesced scan of g_ds slice, collect candidates in bins >= t
  const float* dsrc = &g_ds[(size_t)b*DSZ + c_off[level]];
  for (int i = tid; i < N; i += BS) {
    float d = dsrc[i];
    if (d > 0.0f) {
      int bin = (int)(d * 128.0f);
      bin = bin > NBIN-1 ? NBIN-1 : bin;
      if (bin >= t) {
        int p = atomicAdd(&s_cnt, 1);
        if (p < NBIN) { cs[p] = d; ci[p] = i; }
      }
    }
  }
  __syncthreads();
  int m = s_cnt; if (m > NBIN) m = NBIN;

  // exact conf (matches reference softmax bitwise) for candidates only
  for (int p = tid; p < m; p += BS) {
    float conf = 1.0f / (1.0f + expf(-cs[p]));
    cs[p] = (conf > 0.5f) ? conf : -1.0f;
  }
  int P = 512; while (P < m) P <<= 1;
  for (int i = tid; i < P; i += BS)
    if (i >= m) { cs[i] = -1.0f; ci[i] = 0x7fffffff; }
  __syncthreads();

  // bitonic sort (conf desc, idx asc) over P elements
  for (int k = 2; k <= P; k <<= 1) {
    for (int j = k >> 1; j > 0; j >>= 1) {
      for (int x = tid; x < P; x += BS) {
        int ixj = x ^ j;
        if (ixj > x) {
          float ca = cs[x], cb = cs[ixj];
          int   ia = ci[x], ib = ci[ixj];
          bool later = (ca < cb) || (ca == cb && ia > ib);
          if (later == ((x & k) == 0)) {
            cs[x] = cb; cs[ixj] = ca;
            ci[x] = ib; ci[ixj] = ia;
          }
        }
      }
      __syncthreads();
    }
  }

  // decode + write top-300 (zero-pad shortfall / sub-threshold)
  const float* pb = pred + (size_t)b * N * 6;
  if (tid < KLV) {
    const int o = b*NPROP + level*KLV + tid;
    if (tid < m && cs[tid] > 0.5f) {
      float conf = cs[tid];
      int   idx  = ci[tid];
      int hw = H*W;
      int a  = idx / hw;
      int r2 = idx - a*hw;
      int h  = r2 / W;
      int w  = r2 - h*W;
      const float* pp = pb + (size_t)idx*6;
      float aw = c_anch[level][a].x / stride;
      float ah = c_anch[level][a].y / stride;
      float x  = pp[0]*aw + (float)w;
      float y  = pp[1]*ah + (float)h;
      float bw = expf(pp[2])*aw;
      float bh = expf(pp[3])*ah;
      float x1 = fminf(fmaxf((x - 0.5f*bw)*scale, 0.0f), 1.0f);
      float y1 = fminf(fmaxf((y - 0.5f*bh)*scale, 0.0f), 1.0f);
      float x2 = fminf(fmaxf((x + 0.5f*bw)*scale, 0.0f), 1.0f);
      float y2 = fminf(fmaxf((y + 0.5f*bh)*scale, 0.0f), 1.0f);
      g_box[o]   = make_float4(x1, y1, x2, y2);
      g_score[o] = conf;
      g_src[o]   = (level << 26) | idx;
    } else {
      g_box[o]   = make_float4(0.f, 0.f, 0.f, 0.f);
      g_score[o] = 0.f;
      g_src[o]   = -1;
    }
  }
}

// ---------------- 2) stable 3-way merge of sorted level lists ----------------
__global__ void merge_kernel()
{
  const int b = blockIdx.x;
  const int t = threadIdx.x;   // 1024
  __shared__ float s[NPROP];
  __shared__ float ms[2*KLV];
  __shared__ int   p6[2*KLV];
  __shared__ float fs[NPROP];
  __shared__ int   p9[NPROP];
  __shared__ int   s_nv;

  if (t < NPROP) s[t] = g_score[b*NPROP + t];
  if (t == 0) s_nv = 0;
  __syncthreads();

  // stage 1: merge [0,300) (A) with [300,600) (B); A wins ties
  if (t < 2*KLV) {
    float v; int pos;
    if (t < KLV) {
      v = s[t];
      int lo = 0, hi = KLV;
      while (lo < hi) { int mid = (lo+hi)>>1; if (s[KLV+mid] > v) lo = mid+1; else hi = mid; }
      pos = t + lo;
    } else {
      int j = t - KLV; v = s[t];
      int lo = 0, hi = KLV;
      while (lo < hi) { int mid = (lo+hi)>>1; if (s[mid] >= v) lo = mid+1; else hi = mid; }
      pos = j + lo;
    }
    ms[pos] = v; p6[pos] = t;
  }
  __syncthreads();

  // stage 2: merge AB (600) with C = [600,900); AB wins ties
  if (t < NPROP) {
    float v; int src, pos;
    if (t < 2*KLV) {
      v = ms[t]; src = p6[t];
      int lo = 0, hi = KLV;
      while (lo < hi) { int mid = (lo+hi)>>1; if (s[2*KLV+mid] > v) lo = mid+1; else hi = mid; }
      pos = t + lo;
    } else {
      int j = t - 2*KLV; v = s[t]; src = t;
      int lo = 0, hi = 2*KLV;
      while (lo < hi) { int mid = (lo+hi)>>1; if (ms[mid] >= v) lo = mid+1; else hi = mid; }
      pos = j + lo;
    }
    fs[pos] = v; p9[pos] = src;
  }
  __syncthreads();

  if (t < NPROP) {
    int src = p9[t];
    g_sbox[b*NPROP + t]   = g_box[b*NPROP + src];
    g_sscore[b*NPROP + t] = fs[t];
    g_ssrc[b*NPROP + t]   = g_src[b*NPROP + src];
    if (fs[t] > 0.f && (t == NPROP-1 || fs[t+1] <= 0.f)) s_nv = t + 1;
  }
  __syncthreads();
  if (t == 0) g_nvalid[b] = s_nv;
}

// ------- 3) suppression bitmatrix: one wave, strided rows, float4 staging -------
// One warp per (row, word) task; lane l tests j = w*64+l and j = w*64+32+l.
// Boxes staged as float4 (LDS.128, 4 conflict-free phases) + area array:
// 4 LDS instructions per task-lane instead of 10.
__global__ void supp_kernel()
{
  const int b     = blockIdx.y;
  const int slice = blockIdx.x;        // 0..8
  const int t     = threadIdx.x;       // 1024 = 32 warps
  __shared__ float4 sb4[NPROP];
  __shared__ float  sa[NPROP];
  for (int i = t; i < NPROP; i += 1024) {
    float4 f = g_sbox[b*NPROP + i];
    sb4[i] = f;
    sa[i]  = (f.z - f.x) * (f.w - f.y);
  }
  __syncthreads();

  const int warp = t >> 5;
  const int lane = t & 31;

  // 100 rows x 15 words = 1500 tasks per block
  for (int task = warp; task < 100*NWORDS; task += 32) {
    int k = task / NWORDS;
    int w = task - k*NWORDS;
    int i = slice + 9*k;               // < 900 always (slice<9, k<100)
    u64* dst = &g_supp[((size_t)b*NPROP + i)*NWORDS + w];
    int j0 = w << 6;
    if (j0 + 63 <= i) {                // whole word in lower triangle
      if (lane == 0) *dst = 0ULL;
      continue;
    }
    float4 bi = sb4[i];
    float  ai = sa[i];
    int j1 = j0 + lane;
    int j2 = j1 + 32;
    bool s1, s2;
    if (j0 > i && w != NWORDS-1) {     // interior word: guard-free (warp-uniform)
      {
        float4 bj = sb4[j1];
        float xx1 = fmaxf(bi.x, bj.x);
        float yy1 = fmaxf(bi.y, bj.y);
        float xx2 = fminf(bi.z, bj.z);
        float yy2 = fminf(bi.w, bj.w);
        float inter = fmaxf(xx2 - xx1, 0.f) * fmaxf(yy2 - yy1, 0.f);
        s1 = inter > NMS_THR * (ai + sa[j1] - inter + 1e-9f);
      }
      {
        float4 bj = sb4[j2];
        float xx1 = fmaxf(bi.x, bj.x);
        float yy1 = fmaxf(bi.y, bj.y);
        float xx2 = fminf(bi.z, bj.z);
        float yy2 = fminf(bi.w, bj.w);
        float inter = fmaxf(xx2 - xx1, 0.f) * fmaxf(yy2 - yy1, 0.f);
        s2 = inter > NMS_THR * (ai + sa[j2] - inter + 1e-9f);
      }
    } else {                           // diagonal or tail word
      s1 = false; s2 = false;
      if (j1 > i && j1 < NPROP) {
        float4 bj = sb4[j1];
        float xx1 = fmaxf(bi.x, bj.x);
        float yy1 = fmaxf(bi.y, bj.y);
        float xx2 = fminf(bi.z, bj.z);
        float yy2 = fminf(bi.w, bj.w);
        float inter = fmaxf(xx2 - xx1, 0.f) * fmaxf(yy2 - yy1, 0.f);
        s1 = inter > NMS_THR * (ai + sa[j1] - inter + 1e-9f);
      }
      if (j2 > i && j2 < NPROP) {
        float4 bj = sb4[j2];
        float xx1 = fmaxf(bi.x, bj.x);
        float yy1 = fmaxf(bi.y, bj.y);
        float xx2 = fminf(bi.z, bj.z);
        float yy2 = fminf(bi.w, bj.w);
        float inter = fmaxf(xx2 - xx1, 0.f) * fmaxf(yy2 - yy1, 0.f);
        s2 = inter > NMS_THR * (ai + sa[j2] - inter + 1e-9f);
      }
    }
    unsigned m1 = __ballot_sync(0xffffffffu, s1);
    unsigned m2 = __ballot_sync(0xffffffffu, s2);
    if (lane == 0) *dst = (u64)m1 | ((u64)m2 << 32);
  }
}

// ------- 4) greedy walk per image: warp 0, word-ordered register bitmask -------
// (R12-exact form — measured fastest; further restructurings regressed twice)
__global__ void greedy_kernel()
{
  const int b = blockIdx.x;
  extern __shared__ u64 ssup[];   // 900*15 u64 = 108000 B
  for (int x = threadIdx.x; x < NPROP*NWORDS; x += blockDim.x)
    ssup[x] = g_supp[(size_t)b*NPROP*NWORDS + x];
  __syncthreads();
  if (threadIdx.x >= 32) return;

  const int lane  = threadIdx.x;
  const int lanec = lane < NWORDS ? lane : NWORDS-1;   // clamped accumulate idx
  const int nv    = g_nvalid[b];
  const int nvw   = nv >> 6, nvb = nv & 63;
  u64 valid = (lane < nvw) ? ~0ULL
            : (lane == nvw ? (nvb ? ((1ULL << nvb) - 1ULL) : 0ULL) : 0ULL);
  u64 rem = ~valid;
  int nk = 0;

  for (int w = 0; w < NWORDS && nk < MAXP; w++) {
    u64 cur = ~__shfl_sync(0xffffffffu, rem, w);   // final avail mask, word w
    while (cur != 0 && nk < MAXP) {
      int bit = __ffsll((long long)cur) - 1;
      const u64* rowp = ssup + ((w << 6) + bit) * NWORDS;
      if (lane == 0) g_kept[b*MAXP + nk] = (w << 6) + bit;
      nk++;
      u64 sw = rowp[w];            // broadcast (N=1), critical path
      rem |= rowp[lanec];          // conflict-free / broadcast, off path
      cur = (cur & (cur - 1)) & ~sw;   // clear lowest bit + suppressed
    }
  }
  if (lane == 0) g_nkept[b] = nk;
}

// ------- 5) output: warp-per-row gather + L2-normalize + write (chip-wide) -------
__global__ void write_kernel(float* __restrict__ out,
                             const float* __restrict__ e0,
                             const float* __restrict__ e1,
                             const float* __restrict__ e2)
{
  const int b    = blockIdx.y;
  const int warp = threadIdx.x >> 5;      // 16 warps
  const int lane = threadIdx.x & 31;
  const int r    = blockIdx.x * 16 + warp;  // 32 x 16 = 512 >= 500 rows
  if (r >= MAXP) return;

  float* o = out + ((size_t)b*MAXP + r)*DPROP;

  if (r >= g_nkept[b]) {                  // zero row (output is poisoned)
    #pragma unroll
    for (int k = 0; k < 7; k++) {
      int e = lane + k*32;
      if (e < DPROP) o[e] = 0.0f;
    }
    return;
  }

  const int i   = g_kept[b*MAXP + r];
  const int src = g_ssrc[b*NPROP + i];
  const int level = src >> 26;
  const int idx   = src & ((1 << 26) - 1);
  const int H  = (level == 0) ? 76 : (level == 1 ? 38 : 19);
  const int hw = H*H;
  const int r2 = idx % hw;
  const int h  = r2 / H;
  const int w  = r2 - h*H;
  const float* eb = (level == 0 ? e0 : (level == 1 ? e1 : e2));
  const float* e  = eb + (((size_t)b*H + h)*H + w)*EMB;

  float v[7];
  float p = 0.0f;
  #pragma unroll
  for (int k = 0; k < 7; k++) {
    int x = lane + k*32;
    v[k] = (x < EMB) ? e[x] : 0.0f;
    p += v[k]*v[k];
  }
  #pragma unroll
  for (int s = 16; s > 0; s >>= 1) p += __shfl_xor_sync(0xffffffffu, p, s);
  float rinv = rsqrtf(fmaxf(p, 1e-12f));

  #pragma unroll
  for (int k = 0; k < 7; k++) {
    int x = lane + k*32;
    if (x < EMB) o[5 + x] = v[k] * rinv;
  }
  if (lane == 0) {
    float4 bx = g_sbox[b*NPROP + i];
    o[0] = bx.x; o[1] = bx.y; o[2] = bx.z; o[3] = bx.w;
    o[4] = g_sscore[b*NPROP + i];
  }
}

// ---------------------------------------------------------------------------
extern "C" void kernel_launch(void* const* d_in, const int* in_sizes, int n_in,
                              void* d_out, int out_size)
{
  const float *p0=nullptr,*p1=nullptr,*p2=nullptr,*e0=nullptr,*e1=nullptr,*e2=nullptr;
  for (int i = 0; i < n_in; i++) {
    switch (in_sizes[i]) {
      case 2217984:  p0 = (const float*)d_in[i]; break;  // pred0 [16,4,76,76,6]
      case 554496:   p1 = (const float*)d_in[i]; break;  // pred1 [16,4,38,38,6]
      case 138624:   p2 = (const float*)d_in[i]; break;  // pred2 [16,4,19,19,6]
      case 19222528: e0 = (const float*)d_in[i]; break;  // emb0 [16,76,76,208]
      case 4805632:  e1 = (const float*)d_in[i]; break;  // emb1 [16,38,38,208]
      case 1201408:  e2 = (const float*)d_in[i]; break;  // emb2 [16,19,19,208]
    }
  }

  hist_kernel<<<(NB*DSZ + 1023)/1024, 1024>>>(p0, p1, p2);
  select_kernel<<<dim3(NB,3), 1024>>>(p0, p1, p2);
  merge_kernel<<<NB, 1024>>>();
  supp_kernel<<<dim3(9, NB), 1024>>>();

  cudaFuncSetAttribute(greedy_kernel, cudaFuncAttributeMaxDynamicSharedMemorySize,
                       NPROP*NWORDS*(int)sizeof(u64));
  greedy_kernel<<<NB, 1024, NPROP*NWORDS*sizeof(u64)>>>();

  write_kernel<<<dim3(32, NB), 512>>>((float*)d_out, e0, e1, e2);
}

// round 15
// speedup vs baseline: 1.4240x; 1.0758x over previous
#include <cuda_runtime.h>
#include <cstdint>

typedef unsigned long long u64;

#define NB      16
#define EMB     208
#define KLV     300
#define NPROP   900
#define MAXP    500
#define DPROP   213
#define NWORDS  15      // ceil(900/64)
#define NMS_THR 0.45f
#define NBIN    2048
#define DSZ     30324   // 23104 + 5776 + 1444 per image

__constant__ float2 c_anch[3][4] = {
  {{8.f,24.f},{11.f,34.f},{16.f,48.f},{23.f,68.f}},
  {{32.f,96.f},{45.f,135.f},{64.f,192.f},{90.f,271.f}},
  {{128.f,384.f},{180.f,540.f},{256.f,640.f},{512.f,640.f}}
};
__constant__ int   c_H[3]    = {76, 38, 19};
__constant__ int   c_N[3]    = {23104, 5776, 1444};
__constant__ int   c_off[3]  = {0, 23104, 28880};
__constant__ float c_stride[3] = {8.f, 16.f, 32.f};

// ---------------- device scratch (no allocations allowed) ----------------
__device__ float    g_ds[NB*DSZ];              // d = logit_c - logit_a, [b][r]
__device__ unsigned g_hist[3*NB*NBIN];         // zero-init; re-zeroed each launch
__device__ float4 g_box[NB*NPROP];
__device__ float  g_score[NB*NPROP];
__device__ int    g_src[NB*NPROP];
__device__ float4 g_sbox[NB*NPROP];
__device__ float  g_sscore[NB*NPROP];
__device__ int    g_ssrc[NB*NPROP];
__device__ int    g_nvalid[NB];
__device__ u64    g_supp[NB*NPROP*NWORDS];
__device__ int    g_kept[NB*MAXP];
__device__ int    g_nkept[NB];

// ---- 1a) chip-wide: d = c - a into g_ds + global per-(b,level) histogram ----
__global__ void hist_kernel(const float* __restrict__ p0,
                            const float* __restrict__ p1,
                            const float* __restrict__ p2)
{
  int gid = blockIdx.x*blockDim.x + threadIdx.x;
  if (gid >= NB*DSZ) return;
  int b = gid / DSZ;
  int r = gid - b*DSZ;
  int level, i;
  const float* pred;
  if (r < 23104)      { level = 0; i = r;         pred = p0; }
  else if (r < 28880) { level = 1; i = r - 23104; pred = p1; }
  else                { level = 2; i = r - 28880; pred = p2; }
  const float* pb = pred + (size_t)b * c_N[level] * 6;
  float2 v = *(const float2*)(pb + (size_t)i*6 + 4);
  float d = v.y - v.x;
  g_ds[gid] = d;
  if (d > 0.0f) {
    int bin = (int)(d * 128.0f);
    bin = bin > NBIN-1 ? NBIN-1 : bin;
    atomicAdd(&g_hist[(level*NB + b)*NBIN + bin], 1u);
  }
}

// ---- 1b) per-(image,level): threshold from hist, collect, sort, decode ----
__global__ void select_kernel(const float* __restrict__ p0,
                              const float* __restrict__ p1,
                              const float* __restrict__ p2)
{
  const int b     = blockIdx.x;
  const int level = blockIdx.y;
  const int tid   = threadIdx.x;
  const int BS    = blockDim.x;           // 1024

  const float* pred = (level == 0) ? p0 : (level == 1) ? p1 : p2;
  const int H = c_H[level], W = H;
  const int N = c_N[level];
  const float stride = c_stride[level];
  const float scale  = stride / 608.0f;

  __shared__ unsigned int hist[NBIN];
  __shared__ unsigned int csum[64];
  __shared__ float cs[NBIN];
  __shared__ int   ci[NBIN];
  __shared__ int   s_cnt, s_tbin;

  // load histogram; re-zero global for next replay (determinism invariant)
  unsigned* gh = &g_hist[(level*NB + b)*NBIN];
  for (int i = tid; i < NBIN; i += BS) { hist[i] = gh[i]; gh[i] = 0u; }
  if (tid == 0) s_cnt = 0;
  __syncthreads();

  if (tid < 64) {
    unsigned s = 0;
    #pragma unroll
    for (int k = 0; k < 32; k++) s += hist[tid*32 + k];
    csum[tid] = s;
  }
  __syncthreads();
  if (tid == 0) {
    unsigned acc = 0;
    int t = 0;
    int c = 63;
    for (; c >= 0; c--) {
      if (acc + csum[c] >= (unsigned)KLV) break;
      acc += csum[c];
    }
    if (c >= 0) {
      int bb = c*32 + 31;
      for (; bb > c*32; bb--) {
        if (acc + hist[bb] >= (unsigned)KLV) break;
        acc += hist[bb];
      }
      t = bb;
    }
    s_tbin = t;
  }
  __syncthreads();
  const int t = s_tbin;

  // pass 2: coalesced scan of g_ds slice, collect candidates in bins >= t
  const float* dsrc = &g_ds[(size_t)b*DSZ + c_off[level]];
  for (int i = tid; i < N; i += BS) {
    float d = dsrc[i];
    if (d > 0.0f) {
      int bin = (int)(d * 128.0f);
      bin = bin > NBIN-1 ? NBIN-1 : bin;
      if (bin >= t) {
        int p = atomicAdd(&s_cnt, 1);
        if (p < NBIN) { cs[p] = d; ci[p] = i; }
      }
    }
  }
  __syncthreads();
  int m = s_cnt; if (m > NBIN) m = NBIN;

  // exact conf (matches reference softmax bitwise) for candidates only
  for (int p = tid; p < m; p += BS) {
    float conf = 1.0f / (1.0f + expf(-cs[p]));
    cs[p] = (conf > 0.5f) ? conf : -1.0f;
  }
  int P = 512; while (P < m) P <<= 1;
  for (int i = tid; i < P; i += BS)
    if (i >= m) { cs[i] = -1.0f; ci[i] = 0x7fffffff; }
  __syncthreads();

  // bitonic sort (conf desc, idx asc) over P elements
  for (int k = 2; k <= P; k <<= 1) {
    for (int j = k >> 1; j > 0; j >>= 1) {
      for (int x = tid; x < P; x += BS) {
        int ixj = x ^ j;
        if (ixj > x) {
          float ca = cs[x], cb = cs[ixj];
          int   ia = ci[x], ib = ci[ixj];
          bool later = (ca < cb) || (ca == cb && ia > ib);
          if (later == ((x & k) == 0)) {
            cs[x] = cb; cs[ixj] = ca;
            ci[x] = ib; ci[ixj] = ia;
          }
        }
      }
      __syncthreads();
    }
  }

  // decode + write top-300 (zero-pad shortfall / sub-threshold)
  const float* pb = pred + (size_t)b * N * 6;
  if (tid < KLV) {
    const int o = b*NPROP + level*KLV + tid;
    if (tid < m && cs[tid] > 0.5f) {
      float conf = cs[tid];
      int   idx  = ci[tid];
      int hw = H*W;
      int a  = idx / hw;
      int r2 = idx - a*hw;
      int h  = r2 / W;
      int w  = r2 - h*W;
      const float* pp = pb + (size_t)idx*6;
      float aw = c_anch[level][a].x / stride;
      float ah = c_anch[level][a].y / stride;
      float x  = pp[0]*aw + (float)w;
      float y  = pp[1]*ah + (float)h;
      float bw = expf(pp[2])*aw;
      float bh = expf(pp[3])*ah;
      float x1 = fminf(fmaxf((x - 0.5f*bw)*scale, 0.0f), 1.0f);
      float y1 = fminf(fmaxf((y - 0.5f*bh)*scale, 0.0f), 1.0f);
      float x2 = fminf(fmaxf((x + 0.5f*bw)*scale, 0.0f), 1.0f);
      float y2 = fminf(fmaxf((y + 0.5f*bh)*scale, 0.0f), 1.0f);
      g_box[o]   = make_float4(x1, y1, x2, y2);
      g_score[o] = conf;
      g_src[o]   = (level << 26) | idx;
    } else {
      g_box[o]   = make_float4(0.f, 0.f, 0.f, 0.f);
      g_score[o] = 0.f;
      g_src[o]   = -1;
    }
  }
}

// ---------------- 2) stable 3-way merge of sorted level lists ----------------
__global__ void merge_kernel()
{
  const int b = blockIdx.x;
  const int t = threadIdx.x;   // 1024
  __shared__ float s[NPROP];
  __shared__ float ms[2*KLV];
  __shared__ int   p6[2*KLV];
  __shared__ float fs[NPROP];
  __shared__ int   p9[NPROP];
  __shared__ int   s_nv;

  if (t < NPROP) s[t] = g_score[b*NPROP + t];
  if (t == 0) s_nv = 0;
  __syncthreads();

  // stage 1: merge [0,300) (A) with [300,600) (B); A wins ties
  if (t < 2*KLV) {
    float v; int pos;
    if (t < KLV) {
      v = s[t];
      int lo = 0, hi = KLV;
      while (lo < hi) { int mid = (lo+hi)>>1; if (s[KLV+mid] > v) lo = mid+1; else hi = mid; }
      pos = t + lo;
    } else {
      int j = t - KLV; v = s[t];
      int lo = 0, hi = KLV;
      while (lo < hi) { int mid = (lo+hi)>>1; if (s[mid] >= v) lo = mid+1; else hi = mid; }
      pos = j + lo;
    }
    ms[pos] = v; p6[pos] = t;
  }
  __syncthreads();

  // stage 2: merge AB (600) with C = [600,900); AB wins ties
  if (t < NPROP) {
    float v; int src, pos;
    if (t < 2*KLV) {
      v = ms[t]; src = p6[t];
      int lo = 0, hi = KLV;
      while (lo < hi) { int mid = (lo+hi)>>1; if (s[2*KLV+mid] > v) lo = mid+1; else hi = mid; }
      pos = t + lo;
    } else {
      int j = t - 2*KLV; v = s[t]; src = t;
      int lo = 0, hi = 2*KLV;
      while (lo < hi) { int mid = (lo+hi)>>1; if (ms[mid] >= v) lo = mid+1; else hi = mid; }
      pos = j + lo;
    }
    fs[pos] = v; p9[pos] = src;
  }
  __syncthreads();

  if (t < NPROP) {
    int src = p9[t];
    g_sbox[b*NPROP + t]   = g_box[b*NPROP + src];
    g_sscore[b*NPROP + t] = fs[t];
    g_ssrc[b*NPROP + t]   = g_src[b*NPROP + src];
    if (fs[t] > 0.f && (t == NPROP-1 || fs[t+1] <= 0.f)) s_nv = t + 1;
  }
  __syncthreads();
  if (t == 0) g_nvalid[b] = s_nv;
}

// ------- 3) suppression bitmatrix: warp-per-ROW, strided rows, float4 staging -------
// Each warp owns whole rows (bi/ai loaded once per row). Lower-triangle words
// are zeroed with one lane-parallel store; compute starts at w = i>>6.
__global__ void supp_kernel()
{
  const int b     = blockIdx.y;
  const int slice = blockIdx.x;        // 0..8
  const int t     = threadIdx.x;       // 1024 = 32 warps
  __shared__ float4 sb4[NPROP];
  __shared__ float  sa[NPROP];
  for (int i = t; i < NPROP; i += 1024) {
    float4 f = g_sbox[b*NPROP + i];
    sb4[i] = f;
    sa[i]  = (f.z - f.x) * (f.w - f.y);
  }
  __syncthreads();

  const int warp = t >> 5;
  const int lane = t & 31;

  // 100 rows per block, strided: row k -> i = slice + 9*k
  for (int k = warp; k < 100; k += 32) {
    const int i = slice + 9*k;                       // < 900
    u64* dst = &g_supp[((size_t)b*NPROP + i)*NWORDS];
    const int wstart = i >> 6;
    if (lane < wstart) dst[lane] = 0ULL;             // zero lower-triangle words
    float4 bi = sb4[i];
    float  ai = sa[i];
    for (int w = wstart; w < NWORDS; w++) {
      int j0 = w << 6;
      int j1 = j0 + lane;
      int j2 = j1 + 32;
      bool s1, s2;
      if (j0 > i && w != NWORDS-1) {   // interior word: guard-free (warp-uniform)
        {
          float4 bj = sb4[j1];
          float xx1 = fmaxf(bi.x, bj.x);
          float yy1 = fmaxf(bi.y, bj.y);
          float xx2 = fminf(bi.z, bj.z);
          float yy2 = fminf(bi.w, bj.w);
          float inter = fmaxf(xx2 - xx1, 0.f) * fmaxf(yy2 - yy1, 0.f);
          s1 = inter > NMS_THR * (ai + sa[j1] - inter + 1e-9f);
        }
        {
          float4 bj = sb4[j2];
          float xx1 = fmaxf(bi.x, bj.x);
          float yy1 = fmaxf(bi.y, bj.y);
          float xx2 = fminf(bi.z, bj.z);
          float yy2 = fminf(bi.w, bj.w);
          float inter = fmaxf(xx2 - xx1, 0.f) * fmaxf(yy2 - yy1, 0.f);
          s2 = inter > NMS_THR * (ai + sa[j2] - inter + 1e-9f);
        }
      } else {                         // diagonal or tail word
        s1 = false; s2 = false;
        if (j1 > i && j1 < NPROP) {
          float4 bj = sb4[j1];
          float xx1 = fmaxf(bi.x, bj.x);
          float yy1 = fmaxf(bi.y, bj.y);
          float xx2 = fminf(bi.z, bj.z);
          float yy2 = fminf(bi.w, bj.w);
          float inter = fmaxf(xx2 - xx1, 0.f) * fmaxf(yy2 - yy1, 0.f);
          s1 = inter > NMS_THR * (ai + sa[j1] - inter + 1e-9f);
        }
        if (j2 > i && j2 < NPROP) {
          float4 bj = sb4[j2];
          float xx1 = fmaxf(bi.x, bj.x);
          float yy1 = fmaxf(bi.y, bj.y);
          float xx2 = fminf(bi.z, bj.z);
          float yy2 = fminf(bi.w, bj.w);
          float inter = fmaxf(xx2 - xx1, 0.f) * fmaxf(yy2 - yy1, 0.f);
          s2 = inter > NMS_THR * (ai + sa[j2] - inter + 1e-9f);
        }
      }
      unsigned m1 = __ballot_sync(0xffffffffu, s1);
      unsigned m2 = __ballot_sync(0xffffffffu, s2);
      if (lane == 0) dst[w] = (u64)m1 | ((u64)m2 << 32);
    }
  }
}

// ------- 4) greedy walk per image: warp 0, word-ordered register bitmask -------
// (R12-exact form — measured fastest; further restructurings regressed twice)
__global__ void greedy_kernel()
{
  const int b = blockIdx.x;
  extern __shared__ u64 ssup[];   // 900*15 u64 = 108000 B
  for (int x = threadIdx.x; x < NPROP*NWORDS; x += blockDim.x)
    ssup[x] = g_supp[(size_t)b*NPROP*NWORDS + x];
  __syncthreads();
  if (threadIdx.x >= 32) return;

  const int lane  = threadIdx.x;
  const int lanec = lane < NWORDS ? lane : NWORDS-1;   // clamped accumulate idx
  const int nv    = g_nvalid[b];
  const int nvw   = nv >> 6, nvb = nv & 63;
  u64 valid = (lane < nvw) ? ~0ULL
            : (lane == nvw ? (nvb ? ((1ULL << nvb) - 1ULL) : 0ULL) : 0ULL);
  u64 rem = ~valid;
  int nk = 0;

  for (int w = 0; w < NWORDS && nk < MAXP; w++) {
    u64 cur = ~__shfl_sync(0xffffffffu, rem, w);   // final avail mask, word w
    while (cur != 0 && nk < MAXP) {
      int bit = __ffsll((long long)cur) - 1;
      const u64* rowp = ssup + ((w << 6) + bit) * NWORDS;
      if (lane == 0) g_kept[b*MAXP + nk] = (w << 6) + bit;
      nk++;
      u64 sw = rowp[w];            // broadcast (N=1), critical path
      rem |= rowp[lanec];          // conflict-free / broadcast, off path
      cur = (cur & (cur - 1)) & ~sw;   // clear lowest bit + suppressed
    }
  }
  if (lane == 0) g_nkept[b] = nk;
}

// ------- 5) output: warp-per-row gather + L2-normalize + write (chip-wide) -------
__global__ void write_kernel(float* __restrict__ out,
                             const float* __restrict__ e0,
                             const float* __restrict__ e1,
                             const float* __restrict__ e2)
{
  const int b    = blockIdx.y;
  const int warp = threadIdx.x >> 5;      // 16 warps
  const int lane = threadIdx.x & 31;
  const int r    = blockIdx.x * 16 + warp;  // 32 x 16 = 512 >= 500 rows
  if (r >= MAXP) return;

  float* o = out + ((size_t)b*MAXP + r)*DPROP;

  if (r >= g_nkept[b]) {                  // zero row (output is poisoned)
    #pragma unroll
    for (int k = 0; k < 7; k++) {
      int e = lane + k*32;
      if (e < DPROP) o[e] = 0.0f;
    }
    return;
  }

  const int i   = g_kept[b*MAXP + r];
  const int src = g_ssrc[b*NPROP + i];
  const int level = src >> 26;
  const int idx   = src & ((1 << 26) - 1);
  const int H  = (level == 0) ? 76 : (level == 1 ? 38 : 19);
  const int hw = H*H;
  const int r2 = idx % hw;
  const int h  = r2 / H;
  const int w  = r2 - h*H;
  const float* eb = (level == 0 ? e0 : (level == 1 ? e1 : e2));
  const float* e  = eb + (((size_t)b*H + h)*H + w)*EMB;

  float v[7];
  float p = 0.0f;
  #pragma unroll
  for (int k = 0; k < 7; k++) {
    int x = lane + k*32;
    v[k] = (x < EMB) ? e[x] : 0.0f;
    p += v[k]*v[k];
  }
  #pragma unroll
  for (int s = 16; s > 0; s >>= 1) p += __shfl_xor_sync(0xffffffffu, p, s);
  float rinv = rsqrtf(fmaxf(p, 1e-12f));

  #pragma unroll
  for (int k = 0; k < 7; k++) {
    int x = lane + k*32;
    if (x < EMB) o[5 + x] = v[k] * rinv;
  }
  if (lane == 0) {
    float4 bx = g_sbox[b*NPROP + i];
    o[0] = bx.x; o[1] = bx.y; o[2] = bx.z; o[3] = bx.w;
    o[4] = g_sscore[b*NPROP + i];
  }
}

// ---------------------------------------------------------------------------
extern "C" void kernel_launch(void* const* d_in, const int* in_sizes, int n_in,
                              void* d_out, int out_size)
{
  const float *p0=nullptr,*p1=nullptr,*p2=nullptr,*e0=nullptr,*e1=nullptr,*e2=nullptr;
  for (int i = 0; i < n_in; i++) {
    switch (in_sizes[i]) {
      case 2217984:  p0 = (const float*)d_in[i]; break;  // pred0 [16,4,76,76,6]
      case 554496:   p1 = (const float*)d_in[i]; break;  // pred1 [16,4,38,38,6]
      case 138624:   p2 = (const float*)d_in[i]; break;  // pred2 [16,4,19,19,6]
      case 19222528: e0 = (const float*)d_in[i]; break;  // emb0 [16,76,76,208]
      case 4805632:  e1 = (const float*)d_in[i]; break;  // emb1 [16,38,38,208]
      case 1201408:  e2 = (const float*)d_in[i]; break;  // emb2 [16,19,19,208]
    }
  }

  hist_kernel<<<(NB*DSZ + 1023)/1024, 1024>>>(p0, p1, p2);
  select_kernel<<<dim3(NB,3), 1024>>>(p0, p1, p2);
  merge_kernel<<<NB, 1024>>>();
  supp_kernel<<<dim3(9, NB), 1024>>>();

  cudaFuncSetAttribute(greedy_kernel, cudaFuncAttributeMaxDynamicSharedMemorySize,
                       NPROP*NWORDS*(int)sizeof(u64));
  greedy_kernel<<<NB, 1024, NPROP*NWORDS*sizeof(u64)>>>();

  write_kernel<<<dim3(32, NB), 512>>>((float*)d_out, e0, e1, e2);
}